// round 3
// baseline (speedup 1.0000x reference)
#include <cuda_runtime.h>
#include <math.h>

// Problem constants (fixed shapes for this problem instance)
#define BB 64
#define PP 24564
#define CC 81
#define TT 24
#define THRESH_F 0.5f
#define FULLMASK 0xffffffffu

// ---------------------------------------------------------------------------
// Scratch (device globals — no allocation allowed)
// ---------------------------------------------------------------------------
__device__ unsigned long long g_bp[BB * TT];            // packed (iou_bits<<32)|~p
__device__ float g_closs[(size_t)BB * PP];              // per (b,p) neg conf loss
__device__ double g_loc, g_poscls, g_negcls;            // accumulators
__device__ int g_numpos[BB];
__device__ int g_nsel;                                  // sum_b (num_pos_b + K_b)

// ---------------------------------------------------------------------------
// Kernel 0: zero-init scratch
// ---------------------------------------------------------------------------
__global__ void k_init() {
    int i = blockIdx.x * blockDim.x + threadIdx.x;
    if (i < BB * TT) g_bp[i] = 0ULL;
    if (i < BB) g_numpos[i] = 0;
    if (i == 0) { g_loc = 0.0; g_poscls = 0.0; g_negcls = 0.0; g_nsel = 0; }
}

// ---------------------------------------------------------------------------
// Kernel 1: best prior per (batch, truth): argmax over P of IoU.
// Packed key = (iou_bits << 32) | ~p  -> atomicMax gives max iou, ties -> min p
// (matches jnp.argmax first-index semantics).
// ---------------------------------------------------------------------------
__global__ void k_bestprior(const float* __restrict__ targets,
                            const float* __restrict__ anchors) {
    __shared__ float s_xyxy[TT][4];
    __shared__ unsigned long long s_best[TT];
    const int b = blockIdx.y;
    const int tid = threadIdx.x;

    if (tid < TT) {
        const float* tr = targets + ((size_t)b * TT + tid) * 5;
        s_xyxy[tid][0] = tr[0]; s_xyxy[tid][1] = tr[1];
        s_xyxy[tid][2] = tr[2]; s_xyxy[tid][3] = tr[3];
        s_best[tid] = 0ULL;
    }
    __syncthreads();

    const int p = blockIdx.x * blockDim.x + tid;
    float ax0 = 0.f, ay0 = 0.f, ax1 = 0.f, ay1 = 0.f, aarea = 0.f;
    const bool valid = (p < PP);
    if (valid) {
        float4 a = ((const float4*)anchors)[p];     // cxcywh
        ax0 = a.x - a.z * 0.5f; ay0 = a.y - a.w * 0.5f;
        ax1 = a.x + a.z * 0.5f; ay1 = a.y + a.w * 0.5f;
        aarea = (ax1 - ax0) * (ay1 - ay0);
    }

    for (int t = 0; t < TT; t++) {
        unsigned long long pk = 0ULL;
        if (valid) {
            float tx0 = s_xyxy[t][0], ty0 = s_xyxy[t][1];
            float tx1 = s_xyxy[t][2], ty1 = s_xyxy[t][3];
            float lx = fmaxf(tx0, ax0), ly = fmaxf(ty0, ay0);
            float rx = fminf(tx1, ax1), ry = fminf(ty1, ay1);
            float w = fmaxf(rx - lx, 0.f), h = fmaxf(ry - ly, 0.f);
            float inter = w * h;
            float ta = (tx1 - tx0) * (ty1 - ty0);
            float iou = inter / (ta + aarea - inter);
            pk = ((unsigned long long)__float_as_uint(iou) << 32)
                 | (unsigned long long)(unsigned int)(~p);
        }
        #pragma unroll
        for (int o = 16; o; o >>= 1) {
            unsigned long long other = __shfl_down_sync(FULLMASK, pk, o);
            if (other > pk) pk = other;
        }
        if ((tid & 31) == 0) atomicMax(&s_best[t], pk);
    }
    __syncthreads();
    if (tid < TT) atomicMax(&g_bp[b * TT + tid], s_best[tid]);
}

// ---------------------------------------------------------------------------
// Kernel 2: the 509 MB streaming pass. One warp per (b, p) row.
//  - lse over 81 logits, gather conf[0] and conf[label]
//  - recompute 24 IoUs (lanes 0..23) -> best_truth (max, ties->min t)
//  - scatter membership check (p == best_prior_idx[t], max t wins)
//  - positives: smooth-L1 loc term + (lse - conf[lbl]); write closs
// ---------------------------------------------------------------------------
__global__ void k_main(const float* __restrict__ loc_pred,
                       const float* __restrict__ conf_pred,
                       const float* __restrict__ targets,
                       const float* __restrict__ anchors) {
    __shared__ float s_xyxy[TT][4];
    __shared__ float s_cwh[TT][4];
    __shared__ float s_lbl[TT];
    __shared__ int   s_bp[TT];
    __shared__ double s_loc, s_pcls;
    __shared__ int s_np;

    const int b = blockIdx.y;
    const int tid = threadIdx.x;
    if (tid == 0) { s_loc = 0.0; s_pcls = 0.0; s_np = 0; }
    if (tid < TT) {
        const float* tr = targets + ((size_t)b * TT + tid) * 5;
        float x0 = tr[0], y0 = tr[1], x1 = tr[2], y1 = tr[3];
        s_xyxy[tid][0] = x0; s_xyxy[tid][1] = y0;
        s_xyxy[tid][2] = x1; s_xyxy[tid][3] = y1;
        s_cwh[tid][0] = (x0 + x1) * 0.5f;
        s_cwh[tid][1] = (y0 + y1) * 0.5f;
        s_cwh[tid][2] = x1 - x0;
        s_cwh[tid][3] = y1 - y0;
        s_lbl[tid] = tr[4];
        s_bp[tid] = (int)(~(unsigned int)(g_bp[b * TT + tid] & 0xFFFFFFFFull));
    }
    __syncthreads();

    const int w = tid >> 5, lane = tid & 31;
    const int p = blockIdx.x * (blockDim.x >> 5) + w;

    if (p < PP) {
        const size_t row = (size_t)b * PP + p;
        const float* cp = conf_pred + row * CC;

        // --- logsumexp over 81 ---
        float c0 = cp[lane];
        float c1 = cp[lane + 32];
        float c2 = (lane < CC - 64) ? cp[lane + 64] : -INFINITY;
        float m = fmaxf(fmaxf(c0, c1), c2);
        #pragma unroll
        for (int o = 16; o; o >>= 1) m = fmaxf(m, __shfl_xor_sync(FULLMASK, m, o));
        float s = expf(c0 - m) + expf(c1 - m) + ((lane < CC - 64) ? expf(c2 - m) : 0.f);
        #pragma unroll
        for (int o = 16; o; o >>= 1) s += __shfl_xor_sync(FULLMASK, s, o);
        const float lse = m + logf(s);
        const float conf0 = __shfl_sync(FULLMASK, c0, 0);

        // --- anchor + 24 IoUs (lanes 0..23) ---
        float4 a = ((const float4*)anchors)[p];   // uniform per warp
        float ax0 = a.x - a.z * 0.5f, ay0 = a.y - a.w * 0.5f;
        float ax1 = a.x + a.z * 0.5f, ay1 = a.y + a.w * 0.5f;
        float aarea = (ax1 - ax0) * (ay1 - ay0);

        unsigned long long pk = 0ULL;
        int sc = -1;
        if (lane < TT) {
            float tx0 = s_xyxy[lane][0], ty0 = s_xyxy[lane][1];
            float tx1 = s_xyxy[lane][2], ty1 = s_xyxy[lane][3];
            float lx = fmaxf(tx0, ax0), ly = fmaxf(ty0, ay0);
            float rx = fminf(tx1, ax1), ry = fminf(ty1, ay1);
            float wd = fmaxf(rx - lx, 0.f), ht = fmaxf(ry - ly, 0.f);
            float inter = wd * ht;
            float ta = (tx1 - tx0) * (ty1 - ty0);
            float iou = inter / (ta + aarea - inter);
            pk = ((unsigned long long)__float_as_uint(iou) << 32)
                 | (unsigned long long)(unsigned int)(TT - 1 - lane);
            if (s_bp[lane] == p) sc = lane;   // scatter membership (last t wins)
        }
        #pragma unroll
        for (int o = 16; o; o >>= 1) {
            unsigned long long o1 = __shfl_xor_sync(FULLMASK, pk, o);
            if (o1 > pk) pk = o1;
            int o2 = __shfl_xor_sync(FULLMASK, sc, o);
            sc = max(sc, o2);
        }
        const float bov = __uint_as_float((unsigned int)(pk >> 32));
        const int bt = TT - 1 - (int)(pk & 0xFFFFFFFFull);
        const int match = (bov > THRESH_F) ? bt : sc;   // warp-uniform

        float closs;
        if (match >= 0) {
            closs = 0.f;                                 // positive prior
            const int lbl = (int)s_lbl[match];
            float v0 = __shfl_sync(FULLMASK, c0, lbl & 31);
            float v1 = __shfl_sync(FULLMASK, c1, lbl & 31);
            float v2 = __shfl_sync(FULLMASK, c2, lbl & 31);
            float clbl = (lbl < 32) ? v0 : ((lbl < 64) ? v1 : v2);

            // smooth-L1 loc term, lanes 0..3 one coordinate each
            float locterm = 0.f;
            if (lane < 4) {
                float lp = loc_pred[row * 4 + lane];
                float enc;
                float tcx = s_cwh[match][0], tcy = s_cwh[match][1];
                float tw  = s_cwh[match][2], th  = s_cwh[match][3];
                if (lane == 0)      enc = (tcx - a.x) / a.z;
                else if (lane == 1) enc = (tcy - a.y) / a.w;
                else if (lane == 2) enc = logf(tw) - logf(a.z);
                else                enc = logf(th) - logf(a.w);
                float d = lp - enc;
                float ad = fabsf(d);
                locterm = (ad < 1.f) ? 0.5f * d * d : ad - 0.5f;
            }
            #pragma unroll
            for (int o = 2; o; o >>= 1) locterm += __shfl_xor_sync(FULLMASK, locterm, o);

            if (lane == 0) {
                atomicAdd(&s_loc, (double)locterm);
                atomicAdd(&s_pcls, (double)(lse - clbl));
                atomicAdd(&s_np, 1);
            }
        } else {
            closs = lse - conf0;                         // candidate negative
        }
        if (lane == 0) g_closs[row] = closs;
    }
    __syncthreads();
    if (tid == 0 && s_np) {
        atomicAdd(&g_loc, s_loc);
        atomicAdd(&g_poscls, s_pcls);
        atomicAdd(&g_numpos[b], s_np);
    }
}

// ---------------------------------------------------------------------------
// Kernel 3: per-batch exact K-th-largest via 4x8-bit MSB radix select on float
// bits (closs >= 0 so bits are order-preserving), then sum top-K with ties.
// ---------------------------------------------------------------------------
__global__ void k_select() {
    __shared__ int hist[256];
    __shared__ unsigned int s_sel;
    __shared__ int s_r;
    __shared__ double s_sum;
    __shared__ int s_cnt;

    const int b = blockIdx.x;
    const int tid = threadIdx.x;
    const int np = g_numpos[b];
    long long Kl = 3LL * np;
    if (Kl > PP - 1) Kl = PP - 1;
    const int K = (int)Kl;
    if (K <= 0) {
        if (tid == 0) atomicAdd(&g_nsel, np);
        return;
    }
    const float* cl = g_closs + (size_t)b * PP;

    unsigned int prefix = 0, pmask = 0;
    int r = K;
    for (int shift = 24; shift >= 0; shift -= 8) {
        if (tid < 256) hist[tid] = 0;
        __syncthreads();
        for (int i = tid; i < PP; i += blockDim.x) {
            unsigned int u = __float_as_uint(cl[i]);
            if ((u & pmask) == prefix) atomicAdd(&hist[(u >> shift) & 255], 1);
        }
        __syncthreads();
        if (tid == 0) {
            int cum = 0; unsigned int sel = 0;
            for (int bin = 255; bin >= 0; bin--) {
                int nc = cum + hist[bin];
                if (nc >= r) { sel = (unsigned int)bin; break; }
                cum = nc;
            }
            s_sel = sel; s_r = r - cum;
        }
        __syncthreads();
        prefix |= s_sel << shift;
        pmask |= 0xFFu << shift;
        r = s_r;
        __syncthreads();
    }
    const float theta = __uint_as_float(prefix);   // exact K-th largest

    if (tid == 0) { s_sum = 0.0; s_cnt = 0; }
    __syncthreads();
    double sum = 0.0; int cnt = 0;
    for (int i = tid; i < PP; i += blockDim.x) {
        float v = cl[i];
        if (v > theta) { sum += (double)v; cnt++; }
    }
    #pragma unroll
    for (int o = 16; o; o >>= 1) {
        sum += __shfl_xor_sync(FULLMASK, sum, o);
        cnt += __shfl_xor_sync(FULLMASK, cnt, o);
    }
    if ((tid & 31) == 0) { atomicAdd(&s_sum, sum); atomicAdd(&s_cnt, cnt); }
    __syncthreads();
    if (tid == 0) {
        double negsum = s_sum + (double)(K - s_cnt) * (double)theta;
        atomicAdd(&g_negcls, negsum);
        atomicAdd(&g_nsel, np + K);
    }
}

// ---------------------------------------------------------------------------
// Kernel 4: combine. Non-selected rows each contribute exactly log(C)
// (log-softmax of an all-zero row gathered at class 0).
// ---------------------------------------------------------------------------
__global__ void k_final(float* out) {
    if (threadIdx.x == 0 && blockIdx.x == 0) {
        long long np = 0;
        for (int bb = 0; bb < BB; bb++) np += g_numpos[bb];
        double N = (double)np;
        double cls = g_poscls + g_negcls +
                     (double)((long long)BB * PP - (long long)g_nsel) * log((double)CC);
        out[0] = (float)(g_loc / N);
        out[1] = (float)(cls / N);
    }
}

// ---------------------------------------------------------------------------
// Launch
// ---------------------------------------------------------------------------
extern "C" void kernel_launch(void* const* d_in, const int* in_sizes, int n_in,
                              void* d_out, int out_size) {
    const float *loc = nullptr, *conf = nullptr, *tgt = nullptr, *anc = nullptr;
    for (int i = 0; i < n_in; i++) {
        long long s = in_sizes[i];
        if (s == (long long)BB * PP * 4)       loc  = (const float*)d_in[i];
        else if (s == (long long)BB * PP * CC) conf = (const float*)d_in[i];
        else if (s == (long long)BB * TT * 5)  tgt  = (const float*)d_in[i];
        else if (s == (long long)PP * 4)       anc  = (const float*)d_in[i];
    }
    float* out = (float*)d_out;

    k_init<<<(BB * TT + 255) / 256, 256>>>();

    dim3 g1((PP + 255) / 256, BB);
    k_bestprior<<<g1, 256>>>(tgt, anc);

    dim3 g2((PP + 7) / 8, BB);          // 8 warps/block, one warp per prior row
    k_main<<<g2, 256>>>(loc, conf, tgt, anc);

    k_select<<<BB, 1024>>>();

    k_final<<<1, 1>>>(out);
}